// round 16
// baseline (speedup 1.0000x reference)
#include <cuda_runtime.h>
#include <cuda_bf16.h>
#include <math.h>
#include <stdint.h>

#define N      8192
#define D      128
#define NCLS   128
#define TT     128           // gram tile (rows == cols)
#define NT     (N / TT)      // 64 tiles per dim
#define NTILES 2080          // upper-triangular tiles
#define GNB    296           // persistent gram blocks (one wave at 2 CTA/SM)
#define CAP    128           // max class size supported
#define LDAB   272           // bytes per smem tile row: 128 bf16 + 8 pad
#define SSTR   132           // S matrix row stride (floats)
#define LN2F   0.6931471805599453f

// ---------------- scratch (device globals; no allocations) ----------------
__device__ __nv_bfloat16  g_yhi[N * D];        // bf16(x * invn * sqrt(log2e/T))
__device__ float          g_rowTot[N];         // accumulated via atomicAdd (zeroed in prep)
__device__ float          g_classLoss[NCLS];
__device__ float          g_classN[NCLS];
__device__ int            g_done;              // class_loss last-block counter

// ---------------- helpers ----------------
__device__ __forceinline__ uint32_t smem_u32(const void* p) {
    uint32_t a;
    asm("{ .reg .u64 t; cvta.to.shared.u64 t, %1; cvt.u32.u64 %0, t; }" : "=r"(a) : "l"(p));
    return a;
}
__device__ __forceinline__ float ex2f(float x) {
    float r;
    asm("ex2.approx.ftz.f32 %0, %1;" : "=f"(r) : "f"(x));
    return r;
}
__device__ __forceinline__ float lg2f(float x) {
    float r;
    asm("lg2.approx.f32 %0, %1;" : "=f"(r) : "f"(x));
    return r;
}
__device__ __forceinline__ void cpa16(uint32_t dst, const void* src) {
    asm volatile("{ .reg .u64 g; cvta.to.global.u64 g, %1; cp.async.cg.shared.global [%0], [g], 16; }"
                 :: "r"(dst), "l"(src) : "memory");
}
#define CPA_COMMIT()  asm volatile("cp.async.commit_group;" ::: "memory")
#define CPA_WAIT0()   asm volatile("cp.async.wait_group 0;" ::: "memory")

#define LDSM4(r, addr)                                                           \
    asm volatile("ldmatrix.sync.aligned.m8n8.x4.shared.b16 {%0,%1,%2,%3}, [%4];" \
        : "=r"((r)[0]), "=r"((r)[1]), "=r"((r)[2]), "=r"((r)[3]) : "r"(addr))

#define MMA16816(d, a, b0r, b1r)                                                 \
    asm volatile("mma.sync.aligned.m16n8k16.row.col.f32.bf16.bf16.f32 "          \
        "{%0,%1,%2,%3}, {%4,%5,%6,%7}, {%8,%9}, {%0,%1,%2,%3};"                  \
        : "+f"((d)[0]), "+f"((d)[1]), "+f"((d)[2]), "+f"((d)[3])                 \
        : "r"((a)[0]), "r"((a)[1]), "r"((a)[2]), "r"((a)[3]), "r"(b0r), "r"(b1r))

// ---------------- 1) fused norms + prescale + bf16 + rowTot zero ----------------
__global__ void __launch_bounds__(256) prep_kernel(const float* __restrict__ x) {
    const int warp = threadIdx.x >> 5, lane = threadIdx.x & 31;
    const int row0 = blockIdx.x * 16 + warp * 2;
    float4 v0 = *(const float4*)(x + (size_t)row0 * D + lane * 4);
    float4 v1 = *(const float4*)(x + (size_t)(row0 + 1) * D + lane * 4);
    float s0 = v0.x * v0.x + v0.y * v0.y + v0.z * v0.z + v0.w * v0.w;
    float s1 = v1.x * v1.x + v1.y * v1.y + v1.z * v1.z + v1.w * v1.w;
    #pragma unroll
    for (int o = 16; o > 0; o >>= 1) {
        s0 += __shfl_xor_sync(0xffffffffu, s0, o);
        s1 += __shfl_xor_sync(0xffffffffu, s1, o);
    }
    float a0 = rsqrtf(fmaxf(s0, 1e-12f)) * 2.6858190963521055f;  // invn*sqrt(log2e/T)
    float a1 = rsqrtf(fmaxf(s1, 1e-12f)) * 2.6858190963521055f;
    __nv_bfloat162 p00(__float2bfloat16(v0.x * a0), __float2bfloat16(v0.y * a0));
    __nv_bfloat162 p01(__float2bfloat16(v0.z * a0), __float2bfloat16(v0.w * a0));
    __nv_bfloat162 p10(__float2bfloat16(v1.x * a1), __float2bfloat16(v1.y * a1));
    __nv_bfloat162 p11(__float2bfloat16(v1.z * a1), __float2bfloat16(v1.w * a1));
    uint2 k0, k1;
    k0.x = *(uint32_t*)&p00; k0.y = *(uint32_t*)&p01;
    k1.x = *(uint32_t*)&p10; k1.y = *(uint32_t*)&p11;
    *(uint2*)(g_yhi + (size_t)row0 * D + lane * 4)       = k0;
    *(uint2*)(g_yhi + (size_t)(row0 + 1) * D + lane * 4) = k1;
    if (lane == 0) g_rowTot[row0] = 0.f;
    if (lane == 16) g_rowTot[row0 + 1] = 0.f;
}

// ---------------- 2) persistent HMMA Gram: strip-runs, 1 sync/tile ----------------
#define SM_A     0
#define SM_B0    34816
#define SM_B1    69632
#define SM_RED   104448                  // red 1KB
#define SM_CRED  (SM_RED + 1024)         // colRed double buffer 2 x 2KB
#define SM_TOTAL (SM_CRED + 4096)        // 109568 B -> 2 CTAs/SM

__device__ __forceinline__ void stage_tile(uint32_t dstBase, int rowStart, int tid) {
    for (int i = tid; i < 128 * 16; i += 256) {
        int r = i >> 4, c8 = i & 15;
        cpa16(dstBase + (uint32_t)r * LDAB + (uint32_t)c8 * 16,
              g_yhi + (size_t)(rowStart + r) * D + c8 * 8);
    }
}

__global__ void __launch_bounds__(256, 2) gram_hmma() {
    extern __shared__ char smem[];
    const uint32_t sb = smem_u32(smem);
    const int tid = threadIdx.x, wid = tid >> 5, lane = tid & 31;

    // contiguous tile range [t0, t1) in strip-major order
    const int b = blockIdx.x;
    const int t0 = (b * NTILES) / GNB;
    const int t1 = ((b + 1) * NTILES) / GNB;

    int rt = 0, F = 0;
    while (F + (NT - rt) <= t0) { F += NT - rt; rt++; }
    int ct = rt + (t0 - F);

    stage_tile(sb + SM_A, rt * TT, tid);
    stage_tile(sb + SM_B0, ct * TT, tid);
    CPA_COMMIT();
    CPA_WAIT0();
    __syncthreads();
    int curBuf = 0;

    const int wy = wid & 3, wx = wid >> 2;      // warp grid 4(M) x 2(N)
    const int aRow = wy * 32, bRow = wx * 64;
    const int aR  = aRow + (lane & 15);
    const int aC  = (lane >> 4) * 16;
    const int bR  = bRow + (lane & 7) + ((lane >> 4) << 3);
    const int bC  = ((lane >> 3) & 1) * 16;
    const int g = lane >> 2, t4 = lane & 3;

    float* red     = (float*)(smem + SM_RED);          // [128][2 wx]
    float* colRed0 = (float*)(smem + SM_CRED);         // [128][4 wy]
    float* colRed1 = (float*)(smem + SM_CRED + 2048);

    float rsum[2][2] = {{0.f, 0.f}, {0.f, 0.f}};       // per strip-segment

    for (int t = t0; t < t1; t++) {
        const bool haveNext  = (t + 1 < t1);
        const bool sameStrip = haveNext && (ct + 1 < NT);
        const uint32_t bbase = curBuf ? SM_B1 : SM_B0;
        if (sameStrip) {
            stage_tile(sb + (curBuf ? SM_B0 : SM_B1), (ct + 1) * TT, tid);
            CPA_COMMIT();
        }

        float acc[2][8][4];
        #pragma unroll
        for (int mi = 0; mi < 2; mi++)
            #pragma unroll
            for (int nt = 0; nt < 8; nt++)
                #pragma unroll
                for (int q = 0; q < 4; q++) acc[mi][nt][q] = 0.f;

        #pragma unroll
        for (int kk = 0; kk < 8; kk++) {
            const uint32_t kOff = (uint32_t)kk * 32;
            uint32_t ah[2][4], bh[4][4];
            #pragma unroll
            for (int mi = 0; mi < 2; mi++)
                LDSM4(ah[mi], sb + SM_A + (uint32_t)(aR + mi * 16) * LDAB + kOff + aC);
            #pragma unroll
            for (int ni = 0; ni < 4; ni++)
                LDSM4(bh[ni], sb + bbase + (uint32_t)(bR + ni * 16) * LDAB + kOff + bC);
            #pragma unroll
            for (int mi = 0; mi < 2; mi++)
                #pragma unroll
                for (int ni = 0; ni < 4; ni++)
                    #pragma unroll
                    for (int h = 0; h < 2; h++)
                        MMA16816(acc[mi][ni * 2 + h], ah[mi], bh[ni][h * 2], bh[ni][h * 2 + 1]);
        }

        float* cw = (t & 1) ? colRed1 : colRed0;
        const bool diag = (ct == rt);
        if (!diag) {
            float cs[8][2];
            #pragma unroll
            for (int nt = 0; nt < 8; nt++) { cs[nt][0] = 0.f; cs[nt][1] = 0.f; }
            #pragma unroll
            for (int mi = 0; mi < 2; mi++)
                #pragma unroll
                for (int nt = 0; nt < 8; nt++) {
                    float e0 = ex2f(acc[mi][nt][0]);
                    float e1 = ex2f(acc[mi][nt][1]);
                    float e2 = ex2f(acc[mi][nt][2]);
                    float e3 = ex2f(acc[mi][nt][3]);
                    rsum[mi][0] += e0 + e1;
                    rsum[mi][1] += e2 + e3;
                    cs[nt][0] += e0 + e2;
                    cs[nt][1] += e1 + e3;
                }
            #pragma unroll
            for (int nt = 0; nt < 8; nt++)
                #pragma unroll
                for (int sc = 0; sc < 2; sc++) {
                    float s = cs[nt][sc];
                    s += __shfl_xor_sync(0xffffffffu, s, 4);
                    s += __shfl_xor_sync(0xffffffffu, s, 8);
                    s += __shfl_xor_sync(0xffffffffu, s, 16);
                    if (g == 0) cw[(bRow + nt * 8 + t4 * 2 + sc) * 4 + wy] = s;
                }
        } else {
            #pragma unroll
            for (int mi = 0; mi < 2; mi++) {
                const int row0 = aRow + mi * 16 + g;
                const int row1 = row0 + 8;
                #pragma unroll
                for (int nt = 0; nt < 8; nt++) {
                    const int gc = bRow + nt * 8 + t4 * 2;
                    float e0 = (row0 == gc    ) ? 0.f : ex2f(acc[mi][nt][0]);
                    float e1 = (row0 == gc + 1) ? 0.f : ex2f(acc[mi][nt][1]);
                    float e2 = (row1 == gc    ) ? 0.f : ex2f(acc[mi][nt][2]);
                    float e3 = (row1 == gc + 1) ? 0.f : ex2f(acc[mi][nt][3]);
                    rsum[mi][0] += e0 + e1;
                    rsum[mi][1] += e2 + e3;
                }
            }
        }

        if (sameStrip) CPA_WAIT0();
        __syncthreads();        // B[next] ready + cw visible; single per-tile barrier
        if (!diag && tid < 128)
            atomicAdd(&g_rowTot[ct * TT + tid],
                      (cw[tid * 4] + cw[tid * 4 + 1]) + (cw[tid * 4 + 2] + cw[tid * 4 + 3]));

        if (!sameStrip) {
            // flush this strip-segment's row sums
            #pragma unroll
            for (int mi = 0; mi < 2; mi++)
                #pragma unroll
                for (int hrow = 0; hrow < 2; hrow++) {
                    float s = rsum[mi][hrow];
                    s += __shfl_xor_sync(0xffffffffu, s, 1);
                    s += __shfl_xor_sync(0xffffffffu, s, 2);
                    if (t4 == 0) red[(aRow + mi * 16 + hrow * 8 + g) * 2 + wx] = s;
                    rsum[mi][hrow] = 0.f;
                }
            __syncthreads();
            if (tid < 128)
                atomicAdd(&g_rowTot[rt * TT + tid], red[tid * 2] + red[tid * 2 + 1]);

            if (haveNext) {     // strip change: bubble to restage A + first B
                rt++; ct = rt;
                stage_tile(sb + SM_A, rt * TT, tid);
                stage_tile(sb + (curBuf ? SM_B0 : SM_B1), ct * TT, tid);
                CPA_COMMIT();
                CPA_WAIT0();
                __syncthreads();
            }
        } else {
            ct++;
        }
        curBuf ^= 1;
    }
}

// ---------------- 3) per-class loss: in-block bucketing + guarded 16-warp Gram ----------------
#define CLS_SMEM (128 * LDAB + 128 * SSTR * 4)    // 34816 + 67584 = 102400
__global__ void __launch_bounds__(512, 1) class_loss_kernel(const int* __restrict__ label,
                                                            float* __restrict__ out) {
    extern __shared__ char cs_[];
    char*  tile = cs_;
    float* S    = (float*)(cs_ + 128 * LDAB);     // [128][SSTR]
    __shared__ int   gidx[CAP];
    __shared__ float unsimS[CAP];
    __shared__ float tr[512];
    __shared__ float tp[512];
    __shared__ int   wS[16];
    __shared__ int   shN;
    __shared__ int   isLast;
    const uint32_t sb = smem_u32(tile);
    const int c = blockIdx.x, tid = threadIdx.x, wid = tid >> 5, lane = tid & 31;

    int lab[16];
    {
        const int4* lp = (const int4*)label + tid * 4;
        int4 L0 = lp[0], L1 = lp[1], L2 = lp[2], L3 = lp[3];
        lab[0]=L0.x; lab[1]=L0.y; lab[2]=L0.z; lab[3]=L0.w;
        lab[4]=L1.x; lab[5]=L1.y; lab[6]=L1.z; lab[7]=L1.w;
        lab[8]=L2.x; lab[9]=L2.y; lab[10]=L2.z; lab[11]=L2.w;
        lab[12]=L3.x; lab[13]=L3.y; lab[14]=L3.z; lab[15]=L3.w;
    }
    int myCnt = 0;
    #pragma unroll
    for (int k = 0; k < 16; k++) myCnt += (lab[k] == c);
    int inc = myCnt;
    #pragma unroll
    for (int o = 1; o < 32; o <<= 1) {
        int u = __shfl_up_sync(0xffffffffu, inc, o);
        if (lane >= o) inc += u;
    }
    if (lane == 31) wS[wid] = inc;
    __syncthreads();
    if (tid == 0) {
        int run = 0;
        #pragma unroll
        for (int k = 0; k < 16; k++) { int v = wS[k]; wS[k] = run; run += v; }
        shN = (run < CAP) ? run : CAP;
    }
    __syncthreads();
    {
        int o = wS[wid] + inc - myCnt;
        #pragma unroll
        for (int k = 0; k < 16; k++)
            if (lab[k] == c) { if (o < CAP) gidx[o] = tid * 16 + k; o++; }
    }
    __syncthreads();
    const int n = shN;

    for (int i = tid; i < 128 * 16; i += 512) {
        int r = i >> 4, c8 = i & 15;
        uint32_t off = (uint32_t)r * LDAB + (uint32_t)c8 * 16;
        uint4 v = make_uint4(0u, 0u, 0u, 0u);
        if (r < n) v = ((const uint4*)(g_yhi + (size_t)gidx[r] * D))[c8];
        *(uint4*)(tile + off) = v;
    }
    __syncthreads();

    const int wy = wid & 3, wx = wid >> 2;
    const int aRow = wy * 32, bRow = wx * 32;
    const int aR  = aRow + (lane & 15);
    const int aC  = (lane >> 4) * 16;
    const int bR  = bRow + (lane & 7) + ((lane >> 4) << 3);
    const int bC  = ((lane >> 3) & 1) * 16;
    const int g = lane >> 2, t4 = lane & 3;

    if (aRow < n && bRow < n) {
        float acc[2][4][4];
        #pragma unroll
        for (int mi = 0; mi < 2; mi++)
            #pragma unroll
            for (int nt = 0; nt < 4; nt++)
                #pragma unroll
                for (int q = 0; q < 4; q++) acc[mi][nt][q] = 0.f;

        #pragma unroll
        for (int kk = 0; kk < 8; kk++) {
            const uint32_t kOff = (uint32_t)kk * 32;
            uint32_t ah[2][4], bh[2][4];
            #pragma unroll
            for (int mi = 0; mi < 2; mi++)
                LDSM4(ah[mi], sb + (uint32_t)(aR + mi * 16) * LDAB + kOff + aC);
            #pragma unroll
            for (int ni = 0; ni < 2; ni++)
                LDSM4(bh[ni], sb + (uint32_t)(bR + ni * 16) * LDAB + kOff + bC);
            #pragma unroll
            for (int mi = 0; mi < 2; mi++)
                #pragma unroll
                for (int ni = 0; ni < 2; ni++)
                    #pragma unroll
                    for (int h = 0; h < 2; h++)
                        MMA16816(acc[mi][ni * 2 + h], ah[mi], bh[ni][h * 2], bh[ni][h * 2 + 1]);
        }

        #pragma unroll
        for (int mi = 0; mi < 2; mi++) {
            const int r0 = aRow + mi * 16 + g;
            #pragma unroll
            for (int nt = 0; nt < 4; nt++) {
                const int col = bRow + nt * 8 + t4 * 2;
                *(float2*)&S[r0 * SSTR + col]       = make_float2(acc[mi][nt][0], acc[mi][nt][1]);
                *(float2*)&S[(r0 + 8) * SSTR + col] = make_float2(acc[mi][nt][2], acc[mi][nt][3]);
            }
        }
    }
    __syncthreads();

    for (int i = wid; i < n; i += 16) {
        float ps = 0.f;
        for (int j = lane; j < n; j += 32)
            if (j != i) ps += ex2f(S[i * SSTR + j]);
        #pragma unroll
        for (int o = 16; o > 0; o >>= 1) ps += __shfl_xor_sync(0xffffffffu, ps, o);
        if (lane == 0) unsimS[i] = g_rowTot[gidx[i]] - ps;
    }
    __syncthreads();

    float la = 0.f;
    const int nn = n * n;
    for (int p = tid; p < nn; p += 512) {
        int i = p / n, j = p - i * n;
        if (i == j) continue;
        float s = S[i * SSTR + j];
        la += lg2f(ex2f(s) + unsimS[i]) - s;
    }
    tr[tid] = la * LN2F;
    __syncthreads();
    #pragma unroll
    for (int o = 256; o > 0; o >>= 1) {
        if (tid < o) tr[tid] += tr[tid + o];
        __syncthreads();
    }
    if (tid == 0) {
        g_classLoss[c] = tr[0];
        g_classN[c] = (float)n * (float)(n - 1);
        __threadfence();
        isLast = (atomicAdd(&g_done, 1) == NCLS - 1);
    }
    __syncthreads();
    if (isLast) {
        __threadfence();
        float L = 0.f, P = 0.f;
        if (tid < NCLS) { L = g_classLoss[tid]; P = g_classN[tid]; }
        tr[tid] = L;
        tp[tid] = P;
        __syncthreads();
        #pragma unroll
        for (int o = 64; o > 0; o >>= 1) {
            if (tid < o) { tr[tid] += tr[tid + o]; tp[tid] += tp[tid + o]; }
            __syncthreads();
        }
        if (tid == 0) {
            out[0] = tr[0] / tp[0];
            g_done = 0;   // reset for next graph replay
        }
    }
}

// ---------------- launch ----------------
extern "C" void kernel_launch(void* const* d_in, const int* in_sizes, int n_in,
                              void* d_out, int out_size) {
    const float* x     = (const float*)d_in[0];
    const int*   label = (const int*)d_in[1];
    float*       out   = (float*)d_out;

    cudaFuncSetAttribute(gram_hmma, cudaFuncAttributeMaxDynamicSharedMemorySize, SM_TOTAL);
    cudaFuncSetAttribute(class_loss_kernel, cudaFuncAttributeMaxDynamicSharedMemorySize, CLS_SMEM);

    prep_kernel<<<N / 16, 256>>>(x);
    gram_hmma<<<GNB, 256, SM_TOTAL>>>();
    class_loss_kernel<<<NCLS, 512, CLS_SMEM>>>(label, out);
}

// round 17
// speedup vs baseline: 1.0442x; 1.0442x over previous
#include <cuda_runtime.h>
#include <cuda_bf16.h>
#include <math.h>
#include <stdint.h>

#define N      8192
#define D      128
#define NCLS   128
#define TT     128           // gram tile (rows == cols)
#define NT     (N / TT)      // 64 tiles per dim
#define NBLK   1056          // sum over rt of ceil((64-rt)/2)
#define CAP    128           // max class size supported
#define LDAB   272           // bytes per smem tile row: 128 bf16 + 8 pad
#define SSTR   132           // S matrix row stride (floats)
#define LN2F   0.6931471805599453f

// ---------------- scratch (device globals; no allocations) ----------------
__device__ __nv_bfloat16  g_yhi[N * D];        // bf16(x * invn * sqrt(log2e/T))
__device__ float          g_rowTot[N];         // accumulated via atomicAdd (zeroed in prep)
__device__ float          g_classLoss[NCLS];
__device__ float          g_classN[NCLS];
__device__ int            g_done;              // class_loss last-block counter

// ---------------- helpers ----------------
__device__ __forceinline__ uint32_t smem_u32(const void* p) {
    uint32_t a;
    asm("{ .reg .u64 t; cvta.to.shared.u64 t, %1; cvt.u32.u64 %0, t; }" : "=r"(a) : "l"(p));
    return a;
}
__device__ __forceinline__ float ex2f(float x) {
    float r;
    asm("ex2.approx.ftz.f32 %0, %1;" : "=f"(r) : "f"(x));
    return r;
}
__device__ __forceinline__ float lg2f(float x) {
    float r;
    asm("lg2.approx.f32 %0, %1;" : "=f"(r) : "f"(x));
    return r;
}
__device__ __forceinline__ void cpa16(uint32_t dst, const void* src) {
    asm volatile("{ .reg .u64 g; cvta.to.global.u64 g, %1; cp.async.cg.shared.global [%0], [g], 16; }"
                 :: "r"(dst), "l"(src) : "memory");
}
#define CPA_COMMIT()  asm volatile("cp.async.commit_group;" ::: "memory")
#define CPA_WAIT0()   asm volatile("cp.async.wait_group 0;" ::: "memory")

#define LDSM4(r, addr)                                                           \
    asm volatile("ldmatrix.sync.aligned.m8n8.x4.shared.b16 {%0,%1,%2,%3}, [%4];" \
        : "=r"((r)[0]), "=r"((r)[1]), "=r"((r)[2]), "=r"((r)[3]) : "r"(addr))

#define MMA16816(d, a, b0r, b1r)                                                 \
    asm volatile("mma.sync.aligned.m16n8k16.row.col.f32.bf16.bf16.f32 "          \
        "{%0,%1,%2,%3}, {%4,%5,%6,%7}, {%8,%9}, {%0,%1,%2,%3};"                  \
        : "+f"((d)[0]), "+f"((d)[1]), "+f"((d)[2]), "+f"((d)[3])                 \
        : "r"((a)[0]), "r"((a)[1]), "r"((a)[2]), "r"((a)[3]), "r"(b0r), "r"(b1r))

// ---------------- 1) fused norms + prescale + bf16 + rowTot zero ----------------
__global__ void __launch_bounds__(256) prep_kernel(const float* __restrict__ x) {
    const int warp = threadIdx.x >> 5, lane = threadIdx.x & 31;
    const int row0 = blockIdx.x * 16 + warp * 2;
    float4 v0 = *(const float4*)(x + (size_t)row0 * D + lane * 4);
    float4 v1 = *(const float4*)(x + (size_t)(row0 + 1) * D + lane * 4);
    float s0 = v0.x * v0.x + v0.y * v0.y + v0.z * v0.z + v0.w * v0.w;
    float s1 = v1.x * v1.x + v1.y * v1.y + v1.z * v1.z + v1.w * v1.w;
    #pragma unroll
    for (int o = 16; o > 0; o >>= 1) {
        s0 += __shfl_xor_sync(0xffffffffu, s0, o);
        s1 += __shfl_xor_sync(0xffffffffu, s1, o);
    }
    float a0 = rsqrtf(fmaxf(s0, 1e-12f)) * 2.6858190963521055f;  // invn*sqrt(log2e/T)
    float a1 = rsqrtf(fmaxf(s1, 1e-12f)) * 2.6858190963521055f;
    __nv_bfloat162 p00(__float2bfloat16(v0.x * a0), __float2bfloat16(v0.y * a0));
    __nv_bfloat162 p01(__float2bfloat16(v0.z * a0), __float2bfloat16(v0.w * a0));
    __nv_bfloat162 p10(__float2bfloat16(v1.x * a1), __float2bfloat16(v1.y * a1));
    __nv_bfloat162 p11(__float2bfloat16(v1.z * a1), __float2bfloat16(v1.w * a1));
    uint2 k0, k1;
    k0.x = *(uint32_t*)&p00; k0.y = *(uint32_t*)&p01;
    k1.x = *(uint32_t*)&p10; k1.y = *(uint32_t*)&p11;
    *(uint2*)(g_yhi + (size_t)row0 * D + lane * 4)       = k0;
    *(uint2*)(g_yhi + (size_t)(row0 + 1) * D + lane * 4) = k1;
    if (lane == 0) g_rowTot[row0] = 0.f;
    if (lane == 16) g_rowTot[row0 + 1] = 0.f;
}

// ---------------- 2) HMMA Gram: tile pairs, smem-reduced + atomic rowTot (R15) ----------------
#define SM_A     0
#define SM_B0    34816
#define SM_B1    69632
#define SM_RED   104448                 // red 1KB + colRed 2KB
#define SM_TOTAL (SM_RED + 3072)        // 107520 B -> 2 CTAs/SM

__device__ __forceinline__ void stage_tile(uint32_t dstBase, int rowStart, int tid) {
    for (int i = tid; i < 128 * 16; i += 256) {
        int r = i >> 4, c8 = i & 15;
        cpa16(dstBase + (uint32_t)r * LDAB + (uint32_t)c8 * 16,
              g_yhi + (size_t)(rowStart + r) * D + c8 * 8);
    }
}

__global__ void __launch_bounds__(256, 2) gram_hmma() {
    extern __shared__ char smem[];
    const uint32_t sb = smem_u32(smem);
    const int tid = threadIdx.x, wid = tid >> 5, lane = tid & 31;

    // decode block -> (rt strip, pair of column tiles starting at ct0)
    int b = blockIdx.x, rt = 0;
    for (;;) { int nc = (NT - rt + 1) >> 1; if (b < nc) break; b -= nc; rt++; }
    const int ct0 = rt + b * 2;
    const int ctEnd = (ct0 + 2 < NT) ? (ct0 + 2) : NT;
    const int rowBase = rt * TT;

    stage_tile(sb + SM_A, rowBase, tid);
    if (ct0 != rt) stage_tile(sb + SM_B0, ct0 * TT, tid);
    CPA_COMMIT();
    CPA_WAIT0();
    __syncthreads();

    const int wy = wid & 3, wx = wid >> 2;      // warp grid 4(M) x 2(N)
    const int aRow = wy * 32, bRow = wx * 64;
    const int aR  = aRow + (lane & 15);
    const int aC  = (lane >> 4) * 16;
    const int bR  = bRow + (lane & 7) + ((lane >> 4) << 3);
    const int bC  = ((lane >> 3) & 1) * 16;
    const int g = lane >> 2, t4 = lane & 3;

    float* red    = (float*)(smem + SM_RED);          // [128][2 wx]
    float* colRed = (float*)(smem + SM_RED + 1024);   // [128][4 wy]

    float rsum[2][2] = {{0.f, 0.f}, {0.f, 0.f}};      // accumulates across the pair

    for (int ct = ct0; ct < ctEnd; ct++) {
        const uint32_t bbase = (ct == rt) ? SM_A : (((ct - ct0) & 1) ? SM_B1 : SM_B0);
        const bool pre = (ct + 1 < ctEnd);
        if (pre) {   // prefetch next B while computing this tile
            stage_tile(sb + (((ct + 1 - ct0) & 1) ? SM_B1 : SM_B0), (ct + 1) * TT, tid);
            CPA_COMMIT();
        }

        float acc[2][8][4];
        #pragma unroll
        for (int mi = 0; mi < 2; mi++)
            #pragma unroll
            for (int nt = 0; nt < 8; nt++)
                #pragma unroll
                for (int q = 0; q < 4; q++) acc[mi][nt][q] = 0.f;

        #pragma unroll
        for (int kk = 0; kk < 8; kk++) {
            const uint32_t kOff = (uint32_t)kk * 32;
            uint32_t ah[2][4], bh[4][4];
            #pragma unroll
            for (int mi = 0; mi < 2; mi++)
                LDSM4(ah[mi], sb + SM_A + (uint32_t)(aR + mi * 16) * LDAB + kOff + aC);
            #pragma unroll
            for (int ni = 0; ni < 4; ni++)
                LDSM4(bh[ni], sb + bbase + (uint32_t)(bR + ni * 16) * LDAB + kOff + bC);
            #pragma unroll
            for (int mi = 0; mi < 2; mi++)
                #pragma unroll
                for (int ni = 0; ni < 4; ni++)
                    #pragma unroll
                    for (int h = 0; h < 2; h++)
                        MMA16816(acc[mi][ni * 2 + h], ah[mi], bh[ni][h * 2], bh[ni][h * 2 + 1]);
        }

        if (ct != rt) {
            float cs[8][2];
            #pragma unroll
            for (int nt = 0; nt < 8; nt++) { cs[nt][0] = 0.f; cs[nt][1] = 0.f; }
            #pragma unroll
            for (int mi = 0; mi < 2; mi++)
                #pragma unroll
                for (int nt = 0; nt < 8; nt++) {
                    float e0 = ex2f(acc[mi][nt][0]);
                    float e1 = ex2f(acc[mi][nt][1]);
                    float e2 = ex2f(acc[mi][nt][2]);
                    float e3 = ex2f(acc[mi][nt][3]);
                    rsum[mi][0] += e0 + e1;
                    rsum[mi][1] += e2 + e3;
                    cs[nt][0] += e0 + e2;
                    cs[nt][1] += e1 + e3;
                }
            #pragma unroll
            for (int nt = 0; nt < 8; nt++)
                #pragma unroll
                for (int sc = 0; sc < 2; sc++) {
                    float s = cs[nt][sc];
                    s += __shfl_xor_sync(0xffffffffu, s, 4);
                    s += __shfl_xor_sync(0xffffffffu, s, 8);
                    s += __shfl_xor_sync(0xffffffffu, s, 16);
                    if (g == 0) colRed[(bRow + nt * 8 + t4 * 2 + sc) * 4 + wy] = s;
                }
            __syncthreads();
            if (tid < 128)
                atomicAdd(&g_rowTot[ct * TT + tid],
                          (colRed[tid * 4] + colRed[tid * 4 + 1]) +
                          (colRed[tid * 4 + 2] + colRed[tid * 4 + 3]));
        } else {
            #pragma unroll
            for (int mi = 0; mi < 2; mi++) {
                const int row0 = aRow + mi * 16 + g;
                const int row1 = row0 + 8;
                #pragma unroll
                for (int nt = 0; nt < 8; nt++) {
                    const int gc = bRow + nt * 8 + t4 * 2;
                    float e0 = (row0 == gc    ) ? 0.f : ex2f(acc[mi][nt][0]);
                    float e1 = (row0 == gc + 1) ? 0.f : ex2f(acc[mi][nt][1]);
                    float e2 = (row1 == gc    ) ? 0.f : ex2f(acc[mi][nt][2]);
                    float e3 = (row1 == gc + 1) ? 0.f : ex2f(acc[mi][nt][3]);
                    rsum[mi][0] += e0 + e1;
                    rsum[mi][1] += e2 + e3;
                }
            }
        }
        if (pre) CPA_WAIT0();
        __syncthreads();   // B buffer consumed; colRed reads done
    }

    // pair-accumulated row sums -> atomic add into rowTot
    #pragma unroll
    for (int mi = 0; mi < 2; mi++)
        #pragma unroll
        for (int hrow = 0; hrow < 2; hrow++) {
            float s = rsum[mi][hrow];
            s += __shfl_xor_sync(0xffffffffu, s, 1);
            s += __shfl_xor_sync(0xffffffffu, s, 2);
            if (t4 == 0) red[(aRow + mi * 16 + hrow * 8 + g) * 2 + wx] = s;
        }
    __syncthreads();
    if (tid < 128)
        atomicAdd(&g_rowTot[rowBase + tid], red[tid * 2] + red[tid * 2 + 1]);

#if __CUDA_ARCH__ >= 900
    cudaTriggerProgrammaticLaunchCompletion();
#endif
}

// ---------------- 3) per-class loss: PDL — pre-sync phase overlaps gram tail ----------------
#define CLS_SMEM (128 * LDAB + 128 * SSTR * 4)    // 34816 + 67584 = 102400
__global__ void __launch_bounds__(512, 1) class_loss_kernel(const int* __restrict__ label,
                                                            float* __restrict__ out) {
    extern __shared__ char cs_[];
    char*  tile = cs_;
    float* S    = (float*)(cs_ + 128 * LDAB);     // [128][SSTR]
    __shared__ int   gidx[CAP];
    __shared__ float unsimS[CAP];
    __shared__ float tr[512];
    __shared__ float tp[512];
    __shared__ int   wS[16];
    __shared__ int   shN;
    __shared__ int   isLast;
    const uint32_t sb = smem_u32(tile);
    const int c = blockIdx.x, tid = threadIdx.x, wid = tid >> 5, lane = tid & 31;

    // --- in-block bucketing (depends only on label) ---
    int lab[16];
    {
        const int4* lp = (const int4*)label + tid * 4;
        int4 L0 = lp[0], L1 = lp[1], L2 = lp[2], L3 = lp[3];
        lab[0]=L0.x; lab[1]=L0.y; lab[2]=L0.z; lab[3]=L0.w;
        lab[4]=L1.x; lab[5]=L1.y; lab[6]=L1.z; lab[7]=L1.w;
        lab[8]=L2.x; lab[9]=L2.y; lab[10]=L2.z; lab[11]=L2.w;
        lab[12]=L3.x; lab[13]=L3.y; lab[14]=L3.z; lab[15]=L3.w;
    }
    int myCnt = 0;
    #pragma unroll
    for (int k = 0; k < 16; k++) myCnt += (lab[k] == c);
    int inc = myCnt;
    #pragma unroll
    for (int o = 1; o < 32; o <<= 1) {
        int u = __shfl_up_sync(0xffffffffu, inc, o);
        if (lane >= o) inc += u;
    }
    if (lane == 31) wS[wid] = inc;
    __syncthreads();
    if (tid == 0) {
        int run = 0;
        #pragma unroll
        for (int k = 0; k < 16; k++) { int v = wS[k]; wS[k] = run; run += v; }
        shN = (run < CAP) ? run : CAP;
    }
    __syncthreads();
    {
        int o = wS[wid] + inc - myCnt;
        #pragma unroll
        for (int k = 0; k < 16; k++)
            if (lab[k] == c) { if (o < CAP) gidx[o] = tid * 16 + k; o++; }
    }
    __syncthreads();
    const int n = shN;

    // --- stage class rows (g_yhi written by prep; safe: gram follows prep strictly) ---
    for (int i = tid; i < 128 * 16; i += 512) {
        int r = i >> 4, c8 = i & 15;
        uint32_t off = (uint32_t)r * LDAB + (uint32_t)c8 * 16;
        uint4 v = make_uint4(0u, 0u, 0u, 0u);
        if (r < n) v = ((const uint4*)(g_yhi + (size_t)gidx[r] * D))[c8];
        *(uint4*)(tile + off) = v;
    }
    __syncthreads();

    // --- guarded mini-Gram (no dependency on gram output) ---
    const int wy = wid & 3, wx = wid >> 2;
    const int aRow = wy * 32, bRow = wx * 32;
    const int aR  = aRow + (lane & 15);
    const int aC  = (lane >> 4) * 16;
    const int bR  = bRow + (lane & 7) + ((lane >> 4) << 3);
    const int bC  = ((lane >> 3) & 1) * 16;
    const int g = lane >> 2, t4 = lane & 3;

    if (aRow < n && bRow < n) {
        float acc[2][4][4];
        #pragma unroll
        for (int mi = 0; mi < 2; mi++)
            #pragma unroll
            for (int nt = 0; nt < 4; nt++)
                #pragma unroll
                for (int q = 0; q < 4; q++) acc[mi][nt][q] = 0.f;

        #pragma unroll
        for (int kk = 0; kk < 8; kk++) {
            const uint32_t kOff = (uint32_t)kk * 32;
            uint32_t ah[2][4], bh[2][4];
            #pragma unroll
            for (int mi = 0; mi < 2; mi++)
                LDSM4(ah[mi], sb + (uint32_t)(aR + mi * 16) * LDAB + kOff + aC);
            #pragma unroll
            for (int ni = 0; ni < 2; ni++)
                LDSM4(bh[ni], sb + (uint32_t)(bR + ni * 16) * LDAB + kOff + bC);
            #pragma unroll
            for (int mi = 0; mi < 2; mi++)
                #pragma unroll
                for (int ni = 0; ni < 2; ni++)
                    #pragma unroll
                    for (int h = 0; h < 2; h++)
                        MMA16816(acc[mi][ni * 2 + h], ah[mi], bh[ni][h * 2], bh[ni][h * 2 + 1]);
        }

        #pragma unroll
        for (int mi = 0; mi < 2; mi++) {
            const int r0 = aRow + mi * 16 + g;
            #pragma unroll
            for (int nt = 0; nt < 4; nt++) {
                const int col = bRow + nt * 8 + t4 * 2;
                *(float2*)&S[r0 * SSTR + col]       = make_float2(acc[mi][nt][0], acc[mi][nt][1]);
                *(float2*)&S[(r0 + 8) * SSTR + col] = make_float2(acc[mi][nt][2], acc[mi][nt][3]);
            }
        }
    }
    __syncthreads();

    // --- possum (no rowTot yet) ---
    for (int i = wid; i < n; i += 16) {
        float ps = 0.f;
        for (int j = lane; j < n; j += 32)
            if (j != i) ps += ex2f(S[i * SSTR + j]);
        #pragma unroll
        for (int o = 16; o > 0; o >>= 1) ps += __shfl_xor_sync(0xffffffffu, ps, o);
        if (lane == 0) unsimS[i] = -ps;                // rowTot added after sync
    }
    __syncthreads();

    // --- PDL: wait for gram completion before reading g_rowTot ---
#if __CUDA_ARCH__ >= 900
    cudaGridDependencySynchronize();
#endif
    for (int i = tid; i < n; i += 512) unsimS[i] += g_rowTot[gidx[i]];
    __syncthreads();

    // --- loss terms ---
    float la = 0.f;
    const int nn = n * n;
    for (int p = tid; p < nn; p += 512) {
        int i = p / n, j = p - i * n;
        if (i == j) continue;
        float s = S[i * SSTR + j];
        la += lg2f(ex2f(s) + unsimS[i]) - s;
    }
    tr[tid] = la * LN2F;
    __syncthreads();
    #pragma unroll
    for (int o = 256; o > 0; o >>= 1) {
        if (tid < o) tr[tid] += tr[tid + o];
        __syncthreads();
    }
    if (tid == 0) {
        g_classLoss[c] = tr[0];
        g_classN[c] = (float)n * (float)(n - 1);
        __threadfence();
        isLast = (atomicAdd(&g_done, 1) == NCLS - 1);
    }
    __syncthreads();
    if (isLast) {
        __threadfence();
        float L = 0.f, P = 0.f;
        if (tid < NCLS) { L = g_classLoss[tid]; P = g_classN[tid]; }
        tr[tid] = L;
        tp[tid] = P;
        __syncthreads();
        #pragma unroll
        for (int o = 64; o > 0; o >>= 1) {
            if (tid < o) { tr[tid] += tr[tid + o]; tp[tid] += tp[tid + o]; }
            __syncthreads();
        }
        if (tid == 0) {
            out[0] = tr[0] / tp[0];
            g_done = 0;   // reset for next graph replay
        }
    }
}

// ---------------- launch ----------------
extern "C" void kernel_launch(void* const* d_in, const int* in_sizes, int n_in,
                              void* d_out, int out_size) {
    const float* x     = (const float*)d_in[0];
    const int*   label = (const int*)d_in[1];
    float*       out   = (float*)d_out;

    cudaFuncSetAttribute(gram_hmma, cudaFuncAttributeMaxDynamicSharedMemorySize, SM_TOTAL);
    cudaFuncSetAttribute(class_loss_kernel, cudaFuncAttributeMaxDynamicSharedMemorySize, CLS_SMEM);

    prep_kernel<<<N / 16, 256>>>(x);
    gram_hmma<<<NBLK, 256, SM_TOTAL>>>();

    // class_loss with Programmatic Dependent Launch: pre-sync phase overlaps gram tail
    cudaLaunchConfig_t cfg = {};
    cfg.gridDim = dim3(NCLS, 1, 1);
    cfg.blockDim = dim3(512, 1, 1);
    cfg.dynamicSmemBytes = CLS_SMEM;
    cfg.stream = 0;
    cudaLaunchAttribute attr[1];
    attr[0].id = cudaLaunchAttributeProgrammaticStreamSerialization;
    attr[0].val.programmaticStreamSerializationAllowed = 1;
    cfg.attrs = attr;
    cfg.numAttrs = 1;
    cudaLaunchKernelEx(&cfg, class_loss_kernel, label, out);
}